// round 5
// baseline (speedup 1.0000x reference)
#include <cuda_runtime.h>
#include <cstdint>

#define D_IN  1024
#define D_OUT 1024
#define MAX_N 16384

// ---------------- scratch ---------------------------------------------------
__device__ unsigned g_absmax[2];                  // [0]=x, [1]=w
__device__ int8_t   g_qx[(size_t)MAX_N * D_IN];
__device__ int8_t   g_qw[(size_t)D_OUT * D_IN];

// ---------------- helpers ----------------------------------------------------
__device__ __forceinline__ void cp16(uint32_t s, const void* g) {
    asm volatile("cp.async.cg.shared.global [%0], [%1], 16;" :: "r"(s), "l"(g));
}
#define CP_COMMIT() asm volatile("cp.async.commit_group;" ::: "memory")
#define CP_WAIT0()  asm volatile("cp.async.wait_group 0;"  ::: "memory")

__device__ __forceinline__ uint32_t smem_to_u32(const void* p) {
    uint32_t a;
    asm("{ .reg .u64 t; cvta.to.shared.u64 t, %1; cvt.u32.u64 %0, t; }" : "=r"(a) : "l"(p));
    return a;
}

__device__ __forceinline__ void ldsm_x4(uint32_t& r0, uint32_t& r1, uint32_t& r2, uint32_t& r3,
                                        uint32_t addr) {
    asm volatile("ldmatrix.sync.aligned.m8n8.x4.shared.b16 {%0,%1,%2,%3}, [%4];"
                 : "=r"(r0), "=r"(r1), "=r"(r2), "=r"(r3) : "r"(addr));
}

__device__ __forceinline__ void mma_s8(int* c, const uint32_t* a, const uint32_t* b) {
    asm volatile(
        "mma.sync.aligned.m16n8k32.row.col.s32.s8.s8.s32 "
        "{%0,%1,%2,%3}, {%4,%5,%6,%7}, {%8,%9}, {%0,%1,%2,%3};"
        : "+r"(c[0]), "+r"(c[1]), "+r"(c[2]), "+r"(c[3])
        : "r"(a[0]), "r"(a[1]), "r"(a[2]), "r"(a[3]), "r"(b[0]), "r"(b[1]));
}

// ---------------- kernel 0: reset absmax ------------------------------------
__global__ void init_kernel() { g_absmax[0] = 0u; g_absmax[1] = 0u; }

// ---------------- kernel 1: fused abs-max (MLP-unrolled) --------------------
__global__ void absmax_kernel(const float* __restrict__ x, const float* __restrict__ w,
                              int n4x, int n4w, int xblocks) {
    const bool isx = (int)blockIdx.x < xblocks;
    const float4* p = (const float4*)(isx ? x : w);
    const int n4   = isx ? n4x : n4w;
    const int bid  = isx ? blockIdx.x : blockIdx.x - xblocks;
    const int nblk = isx ? xblocks : (gridDim.x - xblocks);
    const int stride = nblk * blockDim.x;

    unsigned m0 = 0u, m1 = 0u, m2 = 0u, m3 = 0u;
    int i = bid * blockDim.x + threadIdx.x;
    for (; i + 3 * stride < n4; i += 4 * stride) {
        float4 v0 = p[i];
        float4 v1 = p[i + stride];
        float4 v2 = p[i + 2 * stride];
        float4 v3 = p[i + 3 * stride];
        m0 = max(m0, max(max(__float_as_uint(fabsf(v0.x)), __float_as_uint(fabsf(v0.y))),
                         max(__float_as_uint(fabsf(v0.z)), __float_as_uint(fabsf(v0.w)))));
        m1 = max(m1, max(max(__float_as_uint(fabsf(v1.x)), __float_as_uint(fabsf(v1.y))),
                         max(__float_as_uint(fabsf(v1.z)), __float_as_uint(fabsf(v1.w)))));
        m2 = max(m2, max(max(__float_as_uint(fabsf(v2.x)), __float_as_uint(fabsf(v2.y))),
                         max(__float_as_uint(fabsf(v2.z)), __float_as_uint(fabsf(v2.w)))));
        m3 = max(m3, max(max(__float_as_uint(fabsf(v3.x)), __float_as_uint(fabsf(v3.y))),
                         max(__float_as_uint(fabsf(v3.z)), __float_as_uint(fabsf(v3.w)))));
    }
    for (; i < n4; i += stride) {
        float4 v = p[i];
        m0 = max(m0, max(max(__float_as_uint(fabsf(v.x)), __float_as_uint(fabsf(v.y))),
                         max(__float_as_uint(fabsf(v.z)), __float_as_uint(fabsf(v.w)))));
    }
    unsigned m = max(max(m0, m1), max(m2, m3));
    m = __reduce_max_sync(0xffffffffu, m);
    __shared__ unsigned smax[8];
    int warp = threadIdx.x >> 5, lane = threadIdx.x & 31;
    if (lane == 0) smax[warp] = m;
    __syncthreads();
    if (warp == 0) {
        m = (lane < (blockDim.x >> 5)) ? smax[lane] : 0u;
        m = __reduce_max_sync(0xffffffffu, m);
        if (lane == 0) atomicMax(&g_absmax[isx ? 0 : 1], m);
    }
}

// ---------------- kernel 2: fused quantize ----------------------------------
__global__ void quant_kernel(const float* __restrict__ x, const float* __restrict__ w,
                             int8_t* __restrict__ qx, int8_t* __restrict__ qw,
                             int n4x, int n4w, int xblocks) {
    const bool isx = (int)blockIdx.x < xblocks;
    const float4* p = (const float4*)(isx ? x : w);
    int8_t* outp    = isx ? qx : qw;
    const int n4    = isx ? n4x : n4w;
    const int bid   = isx ? blockIdx.x : blockIdx.x - xblocks;
    const int nblk  = isx ? xblocks : (gridDim.x - xblocks);

    float amax  = __uint_as_float(g_absmax[isx ? 0 : 1]);
    float scale = amax / 127.0f;
    float inv   = 1.0f / scale;

    uint* q = (uint*)outp;
    for (int i = bid * blockDim.x + threadIdx.x; i < n4; i += nblk * blockDim.x) {
        float4 v = p[i];
        int c0 = (int)fminf(fmaxf(rintf(v.x * inv), -127.0f), 127.0f);
        int c1 = (int)fminf(fmaxf(rintf(v.y * inv), -127.0f), 127.0f);
        int c2 = (int)fminf(fmaxf(rintf(v.z * inv), -127.0f), 127.0f);
        int c3 = (int)fminf(fmaxf(rintf(v.w * inv), -127.0f), 127.0f);
        q[i] = (uint)(c0 & 0xff) | ((uint)(c1 & 0xff) << 8) |
               ((uint)(c2 & 0xff) << 16) | ((uint)(c3 & 0xff) << 24);
    }
}

// ---------------- kernel 3: hybrid tensor+dp4a int8 GEMM --------------------
// CTA 128x128, K chunks of 128. Warps 0-3: mma.sync cols [0,64).
// Warps 4-7: dp4a cols [64,128). One warp of each kind per SMSP.
#define BM 128
#define BN 128
#define BK 128
#define SSTRIDE 144            // 128 data + 16 pad; conflict-free for ldsm & dp4a
#define NCHUNK (D_IN / BK)     // 8
#define STAGE_B (BM * SSTRIDE) // 18432
#define SMEM_TOTAL (4 * STAGE_B)  // 73728: A[2 stages], B[2 stages]

__global__ __launch_bounds__(256, 2)
void gemm_kernel(const float* __restrict__ bias, float* __restrict__ out) {
    extern __shared__ int8_t smem[];
    int8_t* sA = smem;                       // [2][STAGE_B]
    int8_t* sB = smem + 2 * STAGE_B;         // [2][STAGE_B]

    const int tid  = threadIdx.x;
    const int warp = tid >> 5;
    const int lane = tid & 31;

    const int bm = blockIdx.y * BM;
    const int bn = blockIdx.x * BN;

    const int8_t* gA = g_qx + (size_t)bm * D_IN;
    const int8_t* gB = g_qw + (size_t)bn * D_IN;

    const uint32_t sA0 = smem_to_u32(sA);
    const uint32_t sB0 = smem_to_u32(sB);

    // stage loader: A and B tiles, 128 rows x 128 B each = 1024 chunks16 apiece
    auto stage = [&](int c, int s) {
        const int kb = c * BK;
        int8_t* da = sA + s * STAGE_B;
        int8_t* db = sB + s * STAGE_B;
#pragma unroll
        for (int i = 0; i < 4; i++) {
            int idx = tid + i * 256;
            int row = idx >> 3;
            int col = (idx & 7) * 16;
            cp16(smem_to_u32(&da[row * SSTRIDE + col]), gA + (size_t)row * D_IN + kb + col);
            cp16(smem_to_u32(&db[row * SSTRIDE + col]), gB + (size_t)row * D_IN + kb + col);
        }
        CP_COMMIT();
    };

    const float sc = (__uint_as_float(g_absmax[0]) / 127.0f) *
                     (__uint_as_float(g_absmax[1]) / 127.0f);

    if (warp < 4) {
        // ================= TENSOR path: rows 32*warp..+31, cols 0..63 ======
        const int wm   = warp;
        const int g    = lane >> 2;
        const int tg   = lane & 3;
        const int lrow = lane & 7;
        const int ltil = lane >> 3;
        const int a_row_off = (ltil & 1) * 8 + lrow;
        const int a_col_off = (ltil >> 1) * 16;
        const int b_row_off = (ltil >> 1) * 8 + lrow;
        const int b_col_off = (ltil & 1) * 16;

        int acc[2][8][4];
#pragma unroll
        for (int mt = 0; mt < 2; mt++)
#pragma unroll
            for (int nt = 0; nt < 8; nt++)
#pragma unroll
                for (int i = 0; i < 4; i++) acc[mt][nt][i] = 0;

        stage(0, 0);
        CP_WAIT0();
        __syncthreads();

        for (int c = 0; c < NCHUNK; c++) {
            const int s = c & 1;
            if (c + 1 < NCHUNK) stage(c + 1, s ^ 1);
            const uint32_t aBase = sA0 + (uint32_t)s * STAGE_B;
            const uint32_t bBase = sB0 + (uint32_t)s * STAGE_B;
#pragma unroll
            for (int ks = 0; ks < 4; ks++) {
                const int kk = ks * 32;
                uint32_t a[2][4], b[8][2];
#pragma unroll
                for (int mt = 0; mt < 2; mt++) {
                    uint32_t addr = aBase +
                        (uint32_t)((wm * 32 + mt * 16 + a_row_off) * SSTRIDE + kk + a_col_off);
                    ldsm_x4(a[mt][0], a[mt][1], a[mt][2], a[mt][3], addr);
                }
#pragma unroll
                for (int np = 0; np < 4; np++) {
                    uint32_t addr = bBase +
                        (uint32_t)((np * 16 + b_row_off) * SSTRIDE + kk + b_col_off);
                    ldsm_x4(b[2 * np][0], b[2 * np][1], b[2 * np + 1][0], b[2 * np + 1][1], addr);
                }
#pragma unroll
                for (int mt = 0; mt < 2; mt++)
#pragma unroll
                    for (int nt = 0; nt < 8; nt++)
                        mma_s8(acc[mt][nt], a[mt], b[nt]);
            }
            CP_WAIT0();
            __syncthreads();
        }

        // epilogue (cols bn+0..63)
#pragma unroll
        for (int mt = 0; mt < 2; mt++) {
            int r0 = bm + wm * 32 + mt * 16 + g;
#pragma unroll
            for (int nt = 0; nt < 8; nt++) {
                int c0 = bn + nt * 8 + tg * 2;
                float b0 = __ldg(&bias[c0]);
                float b1 = __ldg(&bias[c0 + 1]);
                float2 v0, v1;
                v0.x = (float)acc[mt][nt][0] * sc + b0;
                v0.y = (float)acc[mt][nt][1] * sc + b1;
                v1.x = (float)acc[mt][nt][2] * sc + b0;
                v1.y = (float)acc[mt][nt][3] * sc + b1;
                *(float2*)&out[(size_t)r0 * D_OUT + c0]       = v0;
                *(float2*)&out[(size_t)(r0 + 8) * D_OUT + c0] = v1;
            }
        }
    } else {
        // ================= DP4A path: rows 32*(warp-4)..+31, cols 64..127 ===
        const int w  = warp - 4;
        const int rb = w * 32;
        const int g4 = lane >> 3;       // 0..3  (rows rb+g4+4i)
        const int g8 = lane & 7;        // 0..7  (cols 64+g8+8j)

        int acc[8][8];
#pragma unroll
        for (int i = 0; i < 8; i++)
#pragma unroll
            for (int j = 0; j < 8; j++) acc[i][j] = 0;

        stage(0, 0);
        CP_WAIT0();
        __syncthreads();

        for (int c = 0; c < NCHUNK; c++) {
            const int s = c & 1;
            if (c + 1 < NCHUNK) stage(c + 1, s ^ 1);

            const int8_t* aT = sA + s * STAGE_B;
            const int8_t* bT = sB + s * STAGE_B;
#pragma unroll
            for (int k8 = 0; k8 < 16; k8++) {
                const int ko = k8 * 8;
                uint2 a[8], b[8];
#pragma unroll
                for (int i = 0; i < 8; i++)
                    a[i] = *(const uint2*)&aT[(rb + g4 + 4 * i) * SSTRIDE + ko];
#pragma unroll
                for (int j = 0; j < 8; j++)
                    b[j] = *(const uint2*)&bT[(64 + g8 + 8 * j) * SSTRIDE + ko];
#pragma unroll
                for (int i = 0; i < 8; i++)
#pragma unroll
                    for (int j = 0; j < 8; j++) {
                        acc[i][j] = __dp4a((int)a[i].x, (int)b[j].x, acc[i][j]);
                        acc[i][j] = __dp4a((int)a[i].y, (int)b[j].y, acc[i][j]);
                    }
            }
            CP_WAIT0();
            __syncthreads();
        }

        // epilogue via smem restage for coalesced stores (stage buffers dead)
        float* smf = (float*)sA + (size_t)w * 2048;   // 32x64 floats per warp
#pragma unroll
        for (int i = 0; i < 8; i++)
#pragma unroll
            for (int j = 0; j < 8; j++) {
                int cl = g8 + 8 * j;
                smf[(g4 + 4 * i) * 64 + cl] =
                    (float)acc[i][j] * sc + __ldg(&bias[bn + 64 + cl]);
            }
        __syncwarp();
#pragma unroll
        for (int rr = 0; rr < 32; rr++) {
            float2 v = *(float2*)&smf[rr * 64 + lane * 2];
            *(float2*)&out[(size_t)(bm + rb + rr) * D_OUT + bn + 64 + lane * 2] = v;
        }
    }
}

// ---------------- launch ----------------------------------------------------
extern "C" void kernel_launch(void* const* d_in, const int* in_sizes, int n_in,
                              void* d_out, int out_size) {
    const float* x      = (const float*)d_in[0];
    const float* weight = (const float*)d_in[1];
    const float* bias   = (const float*)d_in[2];
    float* out          = (float*)d_out;

    const int N   = in_sizes[0] / D_IN;     // 16384
    const int n4x = in_sizes[0] / 4;
    const int n4w = in_sizes[1] / 4;

    int8_t* qx_ptr; cudaGetSymbolAddress((void**)&qx_ptr, g_qx);
    int8_t* qw_ptr; cudaGetSymbolAddress((void**)&qw_ptr, g_qw);

    static int smem_set = 0;
    if (!smem_set) {
        cudaFuncSetAttribute(gemm_kernel, cudaFuncAttributeMaxDynamicSharedMemorySize, SMEM_TOTAL);
        smem_set = 1;
    }

    const int XB = 2048, WB = 128;
    init_kernel<<<1, 1>>>();
    absmax_kernel<<<XB + WB, 256>>>(x, weight, n4x, n4w, XB);
    quant_kernel<<<XB + WB, 256>>>(x, weight, qx_ptr, qw_ptr, n4x, n4w, XB);

    dim3 grid(D_OUT / BN, N / BM);          // (8, 128)
    gemm_kernel<<<grid, 256, SMEM_TOTAL>>>(bias, out);
}

// round 6
// speedup vs baseline: 1.2016x; 1.2016x over previous
#include <cuda_runtime.h>
#include <cstdint>

#define D_IN  1024
#define D_OUT 1024
#define MAX_N 16384

// ---------------- scratch ---------------------------------------------------
__device__ unsigned g_absmax[2];                  // [0]=x, [1]=w
__device__ int8_t   g_qx[(size_t)MAX_N * D_IN];
__device__ int8_t   g_qw[(size_t)D_OUT * D_IN];

// ---------------- helpers ----------------------------------------------------
__device__ __forceinline__ void cp16(uint32_t s, const void* g) {
    asm volatile("cp.async.cg.shared.global [%0], [%1], 16;" :: "r"(s), "l"(g));
}
#define CP_COMMIT() asm volatile("cp.async.commit_group;" ::: "memory")
#define CP_WAIT0()  asm volatile("cp.async.wait_group 0;"  ::: "memory")

__device__ __forceinline__ uint32_t smem_to_u32(const void* p) {
    uint32_t a;
    asm("{ .reg .u64 t; cvta.to.shared.u64 t, %1; cvt.u32.u64 %0, t; }" : "=r"(a) : "l"(p));
    return a;
}

__device__ __forceinline__ void ldsm_x4(uint32_t& r0, uint32_t& r1, uint32_t& r2, uint32_t& r3,
                                        uint32_t addr) {
    asm volatile("ldmatrix.sync.aligned.m8n8.x4.shared.b16 {%0,%1,%2,%3}, [%4];"
                 : "=r"(r0), "=r"(r1), "=r"(r2), "=r"(r3) : "r"(addr));
}

__device__ __forceinline__ void mma_s8(int* c, const uint32_t* a, const uint32_t* b) {
    asm volatile(
        "mma.sync.aligned.m16n8k32.row.col.s32.s8.s8.s32 "
        "{%0,%1,%2,%3}, {%4,%5,%6,%7}, {%8,%9}, {%0,%1,%2,%3};"
        : "+r"(c[0]), "+r"(c[1]), "+r"(c[2]), "+r"(c[3])
        : "r"(a[0]), "r"(a[1]), "r"(a[2]), "r"(a[3]), "r"(b[0]), "r"(b[1]));
}

// ---------------- kernel 0: reset absmax ------------------------------------
__global__ void init_kernel() { g_absmax[0] = 0u; g_absmax[1] = 0u; }

// ---------------- kernel 1: fused abs-max (MLP-unrolled) --------------------
__global__ void absmax_kernel(const float* __restrict__ x, const float* __restrict__ w,
                              int n4x, int n4w, int xblocks) {
    const bool isx = (int)blockIdx.x < xblocks;
    const float4* p = (const float4*)(isx ? x : w);
    const int n4   = isx ? n4x : n4w;
    const int bid  = isx ? blockIdx.x : blockIdx.x - xblocks;
    const int nblk = isx ? xblocks : (gridDim.x - xblocks);
    const int stride = nblk * blockDim.x;

    unsigned m0 = 0u, m1 = 0u, m2 = 0u, m3 = 0u;
    int i = bid * blockDim.x + threadIdx.x;
    for (; i + 3 * stride < n4; i += 4 * stride) {
        float4 v0 = p[i];
        float4 v1 = p[i + stride];
        float4 v2 = p[i + 2 * stride];
        float4 v3 = p[i + 3 * stride];
        m0 = max(m0, max(max(__float_as_uint(fabsf(v0.x)), __float_as_uint(fabsf(v0.y))),
                         max(__float_as_uint(fabsf(v0.z)), __float_as_uint(fabsf(v0.w)))));
        m1 = max(m1, max(max(__float_as_uint(fabsf(v1.x)), __float_as_uint(fabsf(v1.y))),
                         max(__float_as_uint(fabsf(v1.z)), __float_as_uint(fabsf(v1.w)))));
        m2 = max(m2, max(max(__float_as_uint(fabsf(v2.x)), __float_as_uint(fabsf(v2.y))),
                         max(__float_as_uint(fabsf(v2.z)), __float_as_uint(fabsf(v2.w)))));
        m3 = max(m3, max(max(__float_as_uint(fabsf(v3.x)), __float_as_uint(fabsf(v3.y))),
                         max(__float_as_uint(fabsf(v3.z)), __float_as_uint(fabsf(v3.w)))));
    }
    for (; i < n4; i += stride) {
        float4 v = p[i];
        m0 = max(m0, max(max(__float_as_uint(fabsf(v.x)), __float_as_uint(fabsf(v.y))),
                         max(__float_as_uint(fabsf(v.z)), __float_as_uint(fabsf(v.w)))));
    }
    unsigned m = max(max(m0, m1), max(m2, m3));
    m = __reduce_max_sync(0xffffffffu, m);
    __shared__ unsigned smax[8];
    int warp = threadIdx.x >> 5, lane = threadIdx.x & 31;
    if (lane == 0) smax[warp] = m;
    __syncthreads();
    if (warp == 0) {
        m = (lane < (blockDim.x >> 5)) ? smax[lane] : 0u;
        m = __reduce_max_sync(0xffffffffu, m);
        if (lane == 0) atomicMax(&g_absmax[isx ? 0 : 1], m);
    }
}

// ---------------- kernel 2: fused quantize ----------------------------------
__global__ void quant_kernel(const float* __restrict__ x, const float* __restrict__ w,
                             int8_t* __restrict__ qx, int8_t* __restrict__ qw,
                             int n4x, int n4w, int xblocks) {
    const bool isx = (int)blockIdx.x < xblocks;
    const float4* p = (const float4*)(isx ? x : w);
    int8_t* outp    = isx ? qx : qw;
    const int n4    = isx ? n4x : n4w;
    const int bid   = isx ? blockIdx.x : blockIdx.x - xblocks;
    const int nblk  = isx ? xblocks : (gridDim.x - xblocks);

    float amax  = __uint_as_float(g_absmax[isx ? 0 : 1]);
    float scale = amax / 127.0f;
    float inv   = 1.0f / scale;

    uint* q = (uint*)outp;
    for (int i = bid * blockDim.x + threadIdx.x; i < n4; i += nblk * blockDim.x) {
        float4 v = p[i];
        int c0 = (int)fminf(fmaxf(rintf(v.x * inv), -127.0f), 127.0f);
        int c1 = (int)fminf(fmaxf(rintf(v.y * inv), -127.0f), 127.0f);
        int c2 = (int)fminf(fmaxf(rintf(v.z * inv), -127.0f), 127.0f);
        int c3 = (int)fminf(fmaxf(rintf(v.w * inv), -127.0f), 127.0f);
        q[i] = (uint)(c0 & 0xff) | ((uint)(c1 & 0xff) << 8) |
               ((uint)(c2 & 0xff) << 16) | ((uint)(c3 & 0xff) << 24);
    }
}

// ---------------- kernel 3: hybrid tensor+dp4a int8 GEMM --------------------
// CTA 128x64, BK=64. Warps 0-3: mma.sync cols [0,32). Warps 4-7: dp4a cols [32,64).
// 2048 CTAs -> ~6.92 rounds on 296 slots: tiny wave-quantization tail.
#define BM 128
#define BN 64
#define BK 64
#define SSTRIDE 80
#define NCHUNK (D_IN / BK)       // 16
#define STAGE_A (BM * SSTRIDE)   // 10240
#define STAGE_BB (BN * SSTRIDE)  // 5120

__global__ __launch_bounds__(256, 2)
void gemm_kernel(const float* __restrict__ bias, float* __restrict__ out) {
    __shared__ int8_t sA[2][STAGE_A];
    __shared__ int8_t sB[2][STAGE_BB];

    const int tid  = threadIdx.x;
    const int warp = tid >> 5;
    const int lane = tid & 31;

    const int bm = blockIdx.y * BM;
    const int bn = blockIdx.x * BN;

    const int8_t* gA = g_qx + (size_t)bm * D_IN;
    const int8_t* gB = g_qw + (size_t)bn * D_IN;

    const uint32_t sA0 = smem_to_u32(&sA[0][0]);
    const uint32_t sB0 = smem_to_u32(&sB[0][0]);

    // stage: A 128x64B = 512 chunks16 (2/thread), B 64x64B = 256 chunks16 (1/thread)
    auto stage = [&](int c, int s) {
        const int kb = c * BK;
#pragma unroll
        for (int i = 0; i < 2; i++) {
            int idx = tid + i * 256;
            int row = idx >> 2;
            int col = (idx & 3) * 16;
            cp16(smem_to_u32(&sA[s][row * SSTRIDE + col]), gA + (size_t)row * D_IN + kb + col);
        }
        {
            int row = tid >> 2;
            int col = (tid & 3) * 16;
            cp16(smem_to_u32(&sB[s][row * SSTRIDE + col]), gB + (size_t)row * D_IN + kb + col);
        }
        CP_COMMIT();
    };

    const float sc = (__uint_as_float(g_absmax[0]) / 127.0f) *
                     (__uint_as_float(g_absmax[1]) / 127.0f);

    if (warp < 4) {
        // ================= TENSOR path: rows 32*warp..+31, cols 0..31 ======
        const int wm   = warp;
        const int g    = lane >> 2;
        const int tg   = lane & 3;
        const int lrow = lane & 7;
        const int ltil = lane >> 3;
        const int a_row_off = (ltil & 1) * 8 + lrow;
        const int a_col_off = (ltil >> 1) * 16;
        const int b_row_off = (ltil >> 1) * 8 + lrow;
        const int b_col_off = (ltil & 1) * 16;

        int acc[2][4][4];
#pragma unroll
        for (int mt = 0; mt < 2; mt++)
#pragma unroll
            for (int nt = 0; nt < 4; nt++)
#pragma unroll
                for (int i = 0; i < 4; i++) acc[mt][nt][i] = 0;

        stage(0, 0);
        CP_WAIT0();
        __syncthreads();

        for (int c = 0; c < NCHUNK; c++) {
            const int s = c & 1;
            if (c + 1 < NCHUNK) stage(c + 1, s ^ 1);
            const uint32_t aBase = sA0 + (uint32_t)s * STAGE_A;
            const uint32_t bBase = sB0 + (uint32_t)s * STAGE_BB;
#pragma unroll
            for (int ks = 0; ks < 2; ks++) {
                const int kk = ks * 32;
                uint32_t a[2][4], b[4][2];
#pragma unroll
                for (int mt = 0; mt < 2; mt++) {
                    uint32_t addr = aBase +
                        (uint32_t)((wm * 32 + mt * 16 + a_row_off) * SSTRIDE + kk + a_col_off);
                    ldsm_x4(a[mt][0], a[mt][1], a[mt][2], a[mt][3], addr);
                }
#pragma unroll
                for (int np = 0; np < 2; np++) {
                    uint32_t addr = bBase +
                        (uint32_t)((np * 16 + b_row_off) * SSTRIDE + kk + b_col_off);
                    ldsm_x4(b[2 * np][0], b[2 * np][1], b[2 * np + 1][0], b[2 * np + 1][1], addr);
                }
#pragma unroll
                for (int mt = 0; mt < 2; mt++)
#pragma unroll
                    for (int nt = 0; nt < 4; nt++)
                        mma_s8(acc[mt][nt], a[mt], b[nt]);
            }
            CP_WAIT0();
            __syncthreads();
        }

        // epilogue (cols bn+0..31)
#pragma unroll
        for (int mt = 0; mt < 2; mt++) {
            int r0 = bm + wm * 32 + mt * 16 + g;
#pragma unroll
            for (int nt = 0; nt < 4; nt++) {
                int c0 = bn + nt * 8 + tg * 2;
                float b0 = __ldg(&bias[c0]);
                float b1 = __ldg(&bias[c0 + 1]);
                float2 v0, v1;
                v0.x = (float)acc[mt][nt][0] * sc + b0;
                v0.y = (float)acc[mt][nt][1] * sc + b1;
                v1.x = (float)acc[mt][nt][2] * sc + b0;
                v1.y = (float)acc[mt][nt][3] * sc + b1;
                *(float2*)&out[(size_t)r0 * D_OUT + c0]       = v0;
                *(float2*)&out[(size_t)(r0 + 8) * D_OUT + c0] = v1;
            }
        }
    } else {
        // ================= DP4A path: rows 32*(warp-4)..+31, cols 32..63 ===
        const int w  = warp - 4;
        const int rb = w * 32;
        const int g4 = lane >> 3;       // 0..3  (rows rb+g4+4i)
        const int g8 = lane & 7;        // 0..7  (cols 32+g8+8j)

        int acc[8][4];
#pragma unroll
        for (int i = 0; i < 8; i++)
#pragma unroll
            for (int j = 0; j < 4; j++) acc[i][j] = 0;

        stage(0, 0);
        CP_WAIT0();
        __syncthreads();

        for (int c = 0; c < NCHUNK; c++) {
            const int s = c & 1;
            if (c + 1 < NCHUNK) stage(c + 1, s ^ 1);

            const int8_t* aT = &sA[s][0];
            const int8_t* bT = &sB[s][0];
#pragma unroll
            for (int k8 = 0; k8 < 8; k8++) {
                const int ko = k8 * 8;
                uint2 a[8], b[4];
#pragma unroll
                for (int i = 0; i < 8; i++)
                    a[i] = *(const uint2*)&aT[(rb + g4 + 4 * i) * SSTRIDE + ko];
#pragma unroll
                for (int j = 0; j < 4; j++)
                    b[j] = *(const uint2*)&bT[(32 + g8 + 8 * j) * SSTRIDE + ko];
#pragma unroll
                for (int i = 0; i < 8; i++)
#pragma unroll
                    for (int j = 0; j < 4; j++) {
                        acc[i][j] = __dp4a((int)a[i].x, (int)b[j].x, acc[i][j]);
                        acc[i][j] = __dp4a((int)a[i].y, (int)b[j].y, acc[i][j]);
                    }
            }
            CP_WAIT0();
            __syncthreads();
        }

        // epilogue via smem restage (stage buffers dead): 32x32 floats per warp
        float* smf = (float*)&sA[0][0] + (size_t)w * 1024;
#pragma unroll
        for (int i = 0; i < 8; i++)
#pragma unroll
            for (int j = 0; j < 4; j++) {
                int cl = g8 + 8 * j;                 // 0..31
                smf[(g4 + 4 * i) * 32 + cl] =
                    (float)acc[i][j] * sc + __ldg(&bias[bn + 32 + cl]);
            }
        __syncwarp();
#pragma unroll
        for (int rr = 0; rr < 32; rr++) {
            float v = smf[rr * 32 + lane];
            out[(size_t)(bm + rb + rr) * D_OUT + bn + 32 + lane] = v;
        }
    }
}

// ---------------- launch ----------------------------------------------------
extern "C" void kernel_launch(void* const* d_in, const int* in_sizes, int n_in,
                              void* d_out, int out_size) {
    const float* x      = (const float*)d_in[0];
    const float* weight = (const float*)d_in[1];
    const float* bias   = (const float*)d_in[2];
    float* out          = (float*)d_out;

    const int N   = in_sizes[0] / D_IN;     // 16384
    const int n4x = in_sizes[0] / 4;
    const int n4w = in_sizes[1] / 4;

    int8_t* qx_ptr; cudaGetSymbolAddress((void**)&qx_ptr, g_qx);
    int8_t* qw_ptr; cudaGetSymbolAddress((void**)&qw_ptr, g_qw);

    const int XB = 2048, WB = 128;
    init_kernel<<<1, 1>>>();
    absmax_kernel<<<XB + WB, 256>>>(x, weight, n4x, n4w, XB);
    quant_kernel<<<XB + WB, 256>>>(x, weight, qx_ptr, qw_ptr, n4x, n4w, XB);

    dim3 grid(D_OUT / BN, N / BM);          // (16, 128) = 2048 CTAs
    gemm_kernel<<<grid, 256>>>(bias, out);
}